// round 11
// baseline (speedup 1.0000x reference)
#include <cuda_runtime.h>
#include <cstdint>

// ============================================================================
// Two tf32 mma.sync GEMMs (tcgen05 unavailable: harness emits .target sm_100):
//   K1: meas = cumprod8(cos(x @ Wq^T))   -> g_meas scratch
//   K2: out  = meas @ Wo^T               -> d_out
// k = x@Wk^T and v = x@Wv^T are dead compute in the reference; skipped.
// Both einsums: D[m,n] = sum_k A[m,k]*W[n,k] -> m16n8k8.row.col tf32.
//
// R11 = R9 (passing) with ONE change: 256-thread CTAs (8 warps, warp tile
// 64x32, acc 64 regs) -> 16 warps/SM = 4/SMSP, double the latency hiding.
// Fragment k-order and per-element HMMA sequence identical to R2/R9 =>
// bit-identical output (rel_err 4.6e-4).
// ============================================================================

#define BM 128
#define BN 128
#define BK 32
#define KTOT 512
#define MTOT 32768
#define NCHUNK (KTOT / BK)          // 16
#define NTHREADS 256

#define ASTRIDE 36                  // floats per smem row: 32 + 4 pad (bank-safe)
#define TILE_FLOATS (BM * ASTRIDE)  // 4608
#define STAGE_FLOATS (2 * TILE_FLOATS)
#define NSTAGE 3
#define SMEM_BYTES (NSTAGE * STAGE_FLOATS * 4)  // 110592 B

// 64 MB intermediate scratch (device global array: no runtime allocation)
__device__ float g_meas[(size_t)MTOT * KTOT];

// ---------------------------------------------------------------------------
static __device__ __forceinline__ uint32_t smem_u32(const void* p) {
    uint32_t a;
    asm("{ .reg .u64 t; cvta.to.shared.u64 t, %1; cvt.u32.u64 %0, t; }"
        : "=r"(a) : "l"(p));
    return a;
}

// fp32 -> tf32 with round-to-nearest (unbiased; truncation would bias -5e-4)
static __device__ __forceinline__ uint32_t f2tf(float f) {
    uint32_t u;
    asm("cvt.rna.tf32.f32 %0, %1;" : "=r"(u) : "f"(f));
    return u;
}

static __device__ __forceinline__ void cp_async16(uint32_t dst, const void* src) {
    asm volatile("cp.async.cg.shared.global [%0], [%1], 16;"
                 :: "r"(dst), "l"(src) : "memory");
}
static __device__ __forceinline__ void cp_commit() {
    asm volatile("cp.async.commit_group;" ::: "memory");
}
static __device__ __forceinline__ void cp_wait1() {
    asm volatile("cp.async.wait_group 1;" ::: "memory");
}
static __device__ __forceinline__ void cp_wait0() {
    asm volatile("cp.async.wait_group 0;" ::: "memory");
}

static __device__ __forceinline__ void mma_tf32(float* c, const uint32_t* a,
                                                const uint32_t* b) {
    asm volatile(
        "mma.sync.aligned.m16n8k8.row.col.f32.tf32.tf32.f32 "
        "{%0,%1,%2,%3}, {%4,%5,%6,%7}, {%8,%9}, {%0,%1,%2,%3};"
        : "+f"(c[0]), "+f"(c[1]), "+f"(c[2]), "+f"(c[3])
        : "r"(a[0]), "r"(a[1]), "r"(a[2]), "r"(a[3]), "r"(b[0]), "r"(b[1]));
}

// Exclusive-prefix cumprod of cos over one 8-wide head held by a lane quad.
// Thread (tig = lane&3) holds cols 2*tig, 2*tig+1 of its row.
static __device__ __forceinline__ float2 head_scan(float v0, float v1, int tig) {
    const float c0 = __cosf(v0);
    const float c1 = __cosf(v1);
    const float p = c0 * c1;
    const float pm1 = __shfl_up_sync(0xffffffffu, p, 1, 4);
    const float pm2 = __shfl_up_sync(0xffffffffu, p, 2, 4);
    const float pm3 = __shfl_up_sync(0xffffffffu, p, 3, 4);
    float ex = 1.0f;
    if (tig >= 1) ex *= pm1;
    if (tig >= 2) ex *= pm2;
    if (tig >= 3) ex *= pm3;
    float2 r;
    r.x = ex * c0;      // cumprod through col 2*tig
    r.y = ex * p;       // cumprod through col 2*tig+1
    return r;
}

// ---------------------------------------------------------------------------
// D[m_base.., n_base..] = A . W^T over K=512.  8 warps (2x4), warp tile 64x32.
// MEASURE: epilogue = cos+cumprod8 along n -> g_meas.  else -> Outp raw.
// ---------------------------------------------------------------------------
template <bool MEASURE>
__global__ void __launch_bounds__(NTHREADS, 2) qgemm(
    const float* __restrict__ Ain,
    const float* __restrict__ W,
    float* __restrict__ Outp) {
    extern __shared__ float sm[];
    const uint32_t sb = smem_u32(sm);
    const int tid = threadIdx.x;
    const int wid = tid >> 5;
    const int lane = tid & 31;
    const int g = lane >> 2;       // group id (row within fragment)
    const int tig = lane & 3;      // thread-in-group (k / col-pair selector)

    // N-tiles vary fastest (blockIdx.x) so wave-adjacent CTAs share A rows in L2
    const int n_base = blockIdx.x * BN;
    const int m_base = blockIdx.y * BM;

    const float* __restrict__ A = MEASURE ? Ain : g_meas;

    // ---- async stage loader: A tile 128x32 + B tile 128x32, 16B chunks ----
    auto load_stage = [&](int s, int kb) {
        const uint32_t sa = sb + (uint32_t)(s * STAGE_FLOATS) * 4u;
        const uint32_t sw = sa + (uint32_t)TILE_FLOATS * 4u;
#pragma unroll
        for (int i = 0; i < 4; i++) {
            const int p = tid + i * NTHREADS;
            const int row = p >> 3;
            const int c = p & 7;
            cp_async16(sa + (uint32_t)(row * ASTRIDE + c * 4) * 4u,
                       A + (size_t)(m_base + row) * KTOT + kb + c * 4);
        }
#pragma unroll
        for (int i = 0; i < 4; i++) {
            const int p = tid + i * NTHREADS;
            const int row = p >> 3;
            const int c = p & 7;
            cp_async16(sw + (uint32_t)(row * ASTRIDE + c * 4) * 4u,
                       W + (size_t)(n_base + row) * KTOT + kb + c * 4);
        }
        cp_commit();
    };

    load_stage(0, 0);
    load_stage(1, BK);

    const int warp_m = wid & 1;    // 2 x 64 rows
    const int warp_n = wid >> 1;   // 4 x 32 cols

    float acc[4][4][4];
#pragma unroll
    for (int mt = 0; mt < 4; mt++)
#pragma unroll
        for (int nt = 0; nt < 4; nt++)
#pragma unroll
            for (int i = 0; i < 4; i++) acc[mt][nt][i] = 0.0f;

#pragma unroll 1
    for (int kc = 0; kc < NCHUNK; kc++) {
        // group kc must be complete: issued = min(kc+2, NCHUNK) groups so far.
        if (kc == NCHUNK - 1) cp_wait0(); else cp_wait1();
        __syncthreads();

        // Prefetch next stage BEFORE compute: the target stage was consumed
        // last iteration and the sync above ordered all its readers.
        const int nk = kc + 2;
        if (nk < NCHUNK) load_stage(nk % NSTAGE, nk * BK);

        const float* smA = sm + (kc % NSTAGE) * STAGE_FLOATS;
        const float* smB = smA + TILE_FLOATS;

#pragma unroll
        for (int ks = 0; ks < 4; ks++) {
            const int k0 = ks * 8 + tig;
            uint32_t af[4][4];
            uint32_t bf[4][2];
#pragma unroll
            for (int mt = 0; mt < 4; mt++) {
                const int r = warp_m * 64 + mt * 16 + g;
                af[mt][0] = f2tf(smA[r * ASTRIDE + k0]);
                af[mt][1] = f2tf(smA[(r + 8) * ASTRIDE + k0]);
                af[mt][2] = f2tf(smA[r * ASTRIDE + k0 + 4]);
                af[mt][3] = f2tf(smA[(r + 8) * ASTRIDE + k0 + 4]);
            }
#pragma unroll
            for (int nt = 0; nt < 4; nt++) {
                const int n = warp_n * 32 + nt * 8 + g;
                bf[nt][0] = f2tf(smB[n * ASTRIDE + k0]);
                bf[nt][1] = f2tf(smB[n * ASTRIDE + k0 + 4]);
            }
#pragma unroll
            for (int mt = 0; mt < 4; mt++)
#pragma unroll
                for (int nt = 0; nt < 4; nt++)
                    mma_tf32(acc[mt][nt], af[mt], bf[nt]);
        }
    }

    // ---- epilogue ----
    float* __restrict__ Dst = MEASURE ? g_meas : Outp;
#pragma unroll
    for (int mt = 0; mt < 4; mt++) {
#pragma unroll
        for (int nt = 0; nt < 4; nt++) {
            const int r0 = m_base + warp_m * 64 + mt * 16 + g;
            const int n0 = n_base + warp_n * 32 + nt * 8 + 2 * tig;
            const float* c = acc[mt][nt];
            if (MEASURE) {
                // each m16n8 tile spans exactly one 8-wide head (n0 base %8==0)
                const float2 lo = head_scan(c[0], c[1], tig);   // row r0
                const float2 hi = head_scan(c[2], c[3], tig);   // row r0+8
                *(float2*)(Dst + (size_t)r0 * KTOT + n0) = lo;
                *(float2*)(Dst + (size_t)(r0 + 8) * KTOT + n0) = hi;
            } else {
                *(float2*)(Dst + (size_t)r0 * KTOT + n0) =
                    make_float2(c[0], c[1]);
                *(float2*)(Dst + (size_t)(r0 + 8) * KTOT + n0) =
                    make_float2(c[2], c[3]);
            }
        }
    }
}

// ---------------------------------------------------------------------------
// Inputs (metadata order): x, Wq, Wk, Wv, Wo.  Wk/Wv are dead compute.
// ---------------------------------------------------------------------------
extern "C" void kernel_launch(void* const* d_in, const int* in_sizes, int n_in,
                              void* d_out, int out_size) {
    const float* x = (const float*)d_in[0];
    const float* Wq = (const float*)d_in[1];
    const float* Wo = (const float*)d_in[4];

    static bool attr_set = false;
    if (!attr_set) {
        cudaFuncSetAttribute(qgemm<true>,
                             cudaFuncAttributeMaxDynamicSharedMemorySize,
                             SMEM_BYTES);
        cudaFuncSetAttribute(qgemm<false>,
                             cudaFuncAttributeMaxDynamicSharedMemorySize,
                             SMEM_BYTES);
        attr_set = true;
    }

    dim3 grid(KTOT / BN, MTOT / BM);  // (4, 256): n fastest for L2 reuse of A
    qgemm<true><<<grid, NTHREADS, SMEM_BYTES>>>(x, Wq, nullptr);
    qgemm<false><<<grid, NTHREADS, SMEM_BYTES>>>(nullptr, Wo, (float*)d_out);
}

// round 13
// speedup vs baseline: 1.6157x; 1.6157x over previous
#include <cuda_runtime.h>
#include <cuda_fp16.h>
#include <cstdint>

// ============================================================================
// R12 = R2/R10 structure, datatype switched to fp16 (m16n8k16, fp32 accum):
//   pre:  x, Wq, Wo -> half (rne; same 10-bit mantissa as tf32)
//   K1: meas = cumprod8(cos(x_h @ Wq_h^T)) -> g_meash (half)
//   K2: out  = meas_h @ Wo_h^T             -> d_out (fp32)
// k/v are dead compute in the reference; skipped.
// Fragment loads are SCALAR half2 LDS with identity slot mapping (a0 holds
// k=2tig..+1 exactly as the mma expects) — no ldmatrix, no permutation.
// Per warp-chunk: 64 LDS + 64 MMA + 0 cvt  (R2: 128 LDS + 128 cvt + 128 MMA).
// ============================================================================

#define BM 128
#define BN 128
#define BK 32                        // halves of K per chunk (2 k16 steps)
#define KTOT 512
#define MTOT 32768
#define NCHUNK (KTOT / BK)           // 16
#define NTHREADS 128

#define AH 40                        // halves per smem row (32 + 8 pad) = 80 B
#define AH2 (AH / 2)                 // uint32 (half2) per row = 20
#define TILE_H (BM * AH)             // 5120 halves per tile
#define STAGE_H (2 * TILE_H)         // A + B
#define NSTAGE 3
#define SMEM_BYTES (NSTAGE * STAGE_H * 2)   // 61440 B

// Device scratch (static arrays; no runtime allocation)
__device__ __half g_xh[(size_t)MTOT * KTOT];     // 32 MB
__device__ __half g_meash[(size_t)MTOT * KTOT];  // 32 MB
__device__ __half g_wq[KTOT * KTOT];             // 512 KB
__device__ __half g_wo[KTOT * KTOT];             // 512 KB

// ---------------------------------------------------------------------------
static __device__ __forceinline__ uint32_t smem_u32(const void* p) {
    uint32_t a;
    asm("{ .reg .u64 t; cvta.to.shared.u64 t, %1; cvt.u32.u64 %0, t; }"
        : "=r"(a) : "l"(p));
    return a;
}

static __device__ __forceinline__ void cp_async16(uint32_t dst, const void* src) {
    asm volatile("cp.async.cg.shared.global [%0], [%1], 16;"
                 :: "r"(dst), "l"(src) : "memory");
}
static __device__ __forceinline__ void cp_commit() {
    asm volatile("cp.async.commit_group;" ::: "memory");
}
static __device__ __forceinline__ void cp_wait1() {
    asm volatile("cp.async.wait_group 1;" ::: "memory");
}
static __device__ __forceinline__ void cp_wait0() {
    asm volatile("cp.async.wait_group 0;" ::: "memory");
}

// m16n8k16 fp16 inputs, fp32 accumulate
static __device__ __forceinline__ void mma_f16(
    float* c, uint32_t a0, uint32_t a1, uint32_t a2, uint32_t a3,
    uint32_t b0, uint32_t b1) {
    asm volatile(
        "mma.sync.aligned.m16n8k16.row.col.f32.f16.f16.f32 "
        "{%0,%1,%2,%3}, {%4,%5,%6,%7}, {%8,%9}, {%0,%1,%2,%3};"
        : "+f"(c[0]), "+f"(c[1]), "+f"(c[2]), "+f"(c[3])
        : "r"(a0), "r"(a1), "r"(a2), "r"(a3), "r"(b0), "r"(b1));
}

// Exclusive-prefix cumprod of cos over one 8-wide head held by a lane quad.
// Thread (tig = lane&3) holds cols 2*tig, 2*tig+1 of its row.
static __device__ __forceinline__ float2 head_scan(float v0, float v1, int tig) {
    const float c0 = __cosf(v0);
    const float c1 = __cosf(v1);
    const float p = c0 * c1;
    const float pm1 = __shfl_up_sync(0xffffffffu, p, 1, 4);
    const float pm2 = __shfl_up_sync(0xffffffffu, p, 2, 4);
    const float pm3 = __shfl_up_sync(0xffffffffu, p, 3, 4);
    float ex = 1.0f;
    if (tig >= 1) ex *= pm1;
    if (tig >= 2) ex *= pm2;
    if (tig >= 3) ex *= pm3;
    float2 r;
    r.x = ex * c0;      // cumprod through col 2*tig
    r.y = ex * p;       // cumprod through col 2*tig+1
    return r;
}

// ---------------------------------------------------------------------------
// fp32 -> fp16 (rne): DST 0 = x, 1 = Wq, 2 = Wo
// ---------------------------------------------------------------------------
template <int DST>
__global__ void cvt_half(const float* __restrict__ src) {
    __half* __restrict__ dst = (DST == 0) ? g_xh : (DST == 1) ? g_wq : g_wo;
    const size_t i = ((size_t)blockIdx.x * blockDim.x + threadIdx.x) * 8;
    const float4 v0 = *(const float4*)(src + i);
    const float4 v1 = *(const float4*)(src + i + 4);
    const __half2 h0 = __floats2half2_rn(v0.x, v0.y);
    const __half2 h1 = __floats2half2_rn(v0.z, v0.w);
    const __half2 h2 = __floats2half2_rn(v1.x, v1.y);
    const __half2 h3 = __floats2half2_rn(v1.z, v1.w);
    uint4 o;
    o.x = *(const uint32_t*)&h0;
    o.y = *(const uint32_t*)&h1;
    o.z = *(const uint32_t*)&h2;
    o.w = *(const uint32_t*)&h3;
    *(uint4*)(dst + i) = o;
}

// ---------------------------------------------------------------------------
// D[m_base.., n_base..] = A . W^T over K=512.  4 warps, warp tile 64x64.
// MEASURE: epilogue = cos+cumprod8 along n -> g_meash.  else -> Outp (fp32).
// ---------------------------------------------------------------------------
template <bool MEASURE>
__global__ void __launch_bounds__(NTHREADS, 2) qgemm(float* __restrict__ Outp) {
    extern __shared__ __half smh[];
    const uint32_t sb = smem_u32(smh);
    const int tid = threadIdx.x;
    const int wid = tid >> 5;
    const int lane = tid & 31;
    const int g = lane >> 2;       // group id (row / n within fragment)
    const int tig = lane & 3;      // k-pair selector

    // N-tiles vary fastest (blockIdx.x) so wave-adjacent CTAs share A rows in L2
    const int n_base = blockIdx.x * BN;
    const int m_base = blockIdx.y * BM;

    const __half* __restrict__ A = MEASURE ? g_xh : g_meash;
    const __half* __restrict__ W = MEASURE ? g_wq : g_wo;

    // ---- async stage loader: A 128x32h + B 128x32h, 16B granules ----
    // per tile: 128 rows x 4 granules (8 halves each) = 512 granules
    auto load_stage = [&](int s, int kb) {
        const uint32_t sa = sb + (uint32_t)(s * STAGE_H) * 2u;
        const uint32_t sw = sa + (uint32_t)TILE_H * 2u;
#pragma unroll
        for (int i = 0; i < 4; i++) {
            const int p = tid + i * NTHREADS;
            const int row = p >> 2;
            const int c = p & 3;
            cp_async16(sa + (uint32_t)(row * AH + c * 8) * 2u,
                       A + (size_t)(m_base + row) * KTOT + kb + c * 8);
        }
#pragma unroll
        for (int i = 0; i < 4; i++) {
            const int p = tid + i * NTHREADS;
            const int row = p >> 2;
            const int c = p & 3;
            cp_async16(sw + (uint32_t)(row * AH + c * 8) * 2u,
                       W + (size_t)(n_base + row) * KTOT + kb + c * 8);
        }
        cp_commit();
    };

    load_stage(0, 0);
    load_stage(1, BK);

    const int warp_m = wid & 1;    // 2 x 64 rows
    const int warp_n = wid >> 1;   // 2 x 64 cols

    float acc[4][8][4];
#pragma unroll
    for (int mt = 0; mt < 4; mt++)
#pragma unroll
        for (int nt = 0; nt < 8; nt++)
#pragma unroll
            for (int i = 0; i < 4; i++) acc[mt][nt][i] = 0.0f;

#pragma unroll 1
    for (int kc = 0; kc < NCHUNK; kc++) {
        if (kc == NCHUNK - 1) cp_wait0(); else cp_wait1();
        __syncthreads();

        // Prefetch next stage before compute (stage was consumed last iter;
        // the sync above ordered its readers).
        const int nk = kc + 2;
        if (nk < NCHUNK) load_stage(nk % NSTAGE, nk * BK);

        const uint32_t* smA =
            (const uint32_t*)(smh + (kc % NSTAGE) * STAGE_H);
        const uint32_t* smB = smA + TILE_H / 2;

#pragma unroll
        for (int ks = 0; ks < 2; ks++) {       // two k16 steps per chunk
            const int kk = ks * 8;             // half2 offset of this k16 block
            // A fragments: identity slot mapping.
            // a0=(row r,   k 2tig,2tig+1)  a1=(r+8, same)
            // a2=(row r,   k 8+2tig..)     a3=(r+8, same)
            uint32_t af[4][4];
#pragma unroll
            for (int mt = 0; mt < 4; mt++) {
                const int r = warp_m * 64 + mt * 16 + g;
                af[mt][0] = smA[r * AH2 + kk + tig];
                af[mt][1] = smA[(r + 8) * AH2 + kk + tig];
                af[mt][2] = smA[r * AH2 + kk + tig + 4];
                af[mt][3] = smA[(r + 8) * AH2 + kk + tig + 4];
            }
            uint32_t bf[8][2];
#pragma unroll
            for (int nt = 0; nt < 8; nt++) {
                const int n = warp_n * 64 + nt * 8 + g;
                bf[nt][0] = smB[n * AH2 + kk + tig];        // k 2tig,2tig+1
                bf[nt][1] = smB[n * AH2 + kk + tig + 4];    // k 8+2tig..
            }
#pragma unroll
            for (int mt = 0; mt < 4; mt++)
#pragma unroll
                for (int nt = 0; nt < 8; nt++)
                    mma_f16(acc[mt][nt], af[mt][0], af[mt][1], af[mt][2],
                            af[mt][3], bf[nt][0], bf[nt][1]);
        }
    }

    // ---- epilogue: c0=(g,2tig) c1=(g,2tig+1) c2=(g+8,2tig) c3=(g+8,2tig+1)
#pragma unroll
    for (int mt = 0; mt < 4; mt++) {
#pragma unroll
        for (int nt = 0; nt < 8; nt++) {
            const int r0 = m_base + warp_m * 64 + mt * 16 + g;
            const int n0 = n_base + warp_n * 64 + nt * 8 + 2 * tig;
            const float* c = acc[mt][nt];
            if (MEASURE) {
                // each m16n8 tile spans exactly one 8-wide head
                const float2 lo = head_scan(c[0], c[1], tig);   // row r0
                const float2 hi = head_scan(c[2], c[3], tig);   // row r0+8
                const __half2 hlo = __floats2half2_rn(lo.x, lo.y);
                const __half2 hhi = __floats2half2_rn(hi.x, hi.y);
                *(__half2*)(g_meash + (size_t)r0 * KTOT + n0) = hlo;
                *(__half2*)(g_meash + (size_t)(r0 + 8) * KTOT + n0) = hhi;
            } else {
                *(float2*)(Outp + (size_t)r0 * KTOT + n0) =
                    make_float2(c[0], c[1]);
                *(float2*)(Outp + (size_t)(r0 + 8) * KTOT + n0) =
                    make_float2(c[2], c[3]);
            }
        }
    }
}

// ---------------------------------------------------------------------------
// Inputs (metadata order): x, Wq, Wk, Wv, Wo.  Wk/Wv are dead compute.
// ---------------------------------------------------------------------------
extern "C" void kernel_launch(void* const* d_in, const int* in_sizes, int n_in,
                              void* d_out, int out_size) {
    const float* x = (const float*)d_in[0];
    const float* Wq = (const float*)d_in[1];
    const float* Wo = (const float*)d_in[4];

    static bool attr_set = false;
    if (!attr_set) {
        cudaFuncSetAttribute(qgemm<true>,
                             cudaFuncAttributeMaxDynamicSharedMemorySize,
                             SMEM_BYTES);
        cudaFuncSetAttribute(qgemm<false>,
                             cudaFuncAttributeMaxDynamicSharedMemorySize,
                             SMEM_BYTES);
        attr_set = true;
    }

    const size_t XN = (size_t)MTOT * KTOT;   // 16777216
    const size_t WN = (size_t)KTOT * KTOT;   // 262144
    cvt_half<0><<<(unsigned)(XN / (256 * 8)), 256>>>(x);
    cvt_half<1><<<(unsigned)(WN / (256 * 8)), 256>>>(Wq);
    cvt_half<2><<<(unsigned)(WN / (256 * 8)), 256>>>(Wo);

    dim3 grid(KTOT / BN, MTOT / BM);  // (4, 256): n fastest for L2 reuse of A
    qgemm<true><<<grid, NTHREADS, SMEM_BYTES>>>(nullptr);
    qgemm<false><<<grid, NTHREADS, SMEM_BYTES>>>((float*)d_out);
}

// round 14
// speedup vs baseline: 1.7470x; 1.0813x over previous
#include <cuda_runtime.h>
#include <cuda_fp16.h>
#include <cstdint>

// ============================================================================
// R14 = R12 (passing, 166us) with ONE change: BK 32 -> 64 (8 chunks, half the
// barriers, 2x deeper ILP window). Indexing/numerics untouched -> bit-identical.
//   pre:  x, Wq, Wo -> half (rne)
//   K1: meas = cumprod8(cos(x_h @ Wq_h^T)) -> g_meash (half)
//   K2: out  = meas_h @ Wo_h^T             -> d_out (fp32)
// k/v are dead compute in the reference; skipped.
// Fragment loads: SCALAR half2 LDS, identity slot mapping (proven correct).
// ============================================================================

#define BM 128
#define BN 128
#define BK 64                        // halves of K per chunk (4 k16 steps)
#define KTOT 512
#define MTOT 32768
#define NCHUNK (KTOT / BK)           // 8
#define NTHREADS 128

#define AH 72                        // halves per smem row (64 + 8 pad) = 144B
#define AH2 (AH / 2)                 // half2 per row = 36 (banks 4g+tig: clean)
#define TILE_H (BM * AH)             // 9216 halves per tile
#define STAGE_H (2 * TILE_H)         // A + B
#define NSTAGE 3
#define SMEM_BYTES (NSTAGE * STAGE_H * 2)   // 110592 B

// Device scratch (static arrays; no runtime allocation)
__device__ __half g_xh[(size_t)MTOT * KTOT];     // 32 MB
__device__ __half g_meash[(size_t)MTOT * KTOT];  // 32 MB
__device__ __half g_wq[KTOT * KTOT];             // 512 KB
__device__ __half g_wo[KTOT * KTOT];             // 512 KB

// ---------------------------------------------------------------------------
static __device__ __forceinline__ uint32_t smem_u32(const void* p) {
    uint32_t a;
    asm("{ .reg .u64 t; cvta.to.shared.u64 t, %1; cvt.u32.u64 %0, t; }"
        : "=r"(a) : "l"(p));
    return a;
}

static __device__ __forceinline__ void cp_async16(uint32_t dst, const void* src) {
    asm volatile("cp.async.cg.shared.global [%0], [%1], 16;"
                 :: "r"(dst), "l"(src) : "memory");
}
static __device__ __forceinline__ void cp_commit() {
    asm volatile("cp.async.commit_group;" ::: "memory");
}
static __device__ __forceinline__ void cp_wait1() {
    asm volatile("cp.async.wait_group 1;" ::: "memory");
}
static __device__ __forceinline__ void cp_wait0() {
    asm volatile("cp.async.wait_group 0;" ::: "memory");
}

// m16n8k16 fp16 inputs, fp32 accumulate
static __device__ __forceinline__ void mma_f16(
    float* c, uint32_t a0, uint32_t a1, uint32_t a2, uint32_t a3,
    uint32_t b0, uint32_t b1) {
    asm volatile(
        "mma.sync.aligned.m16n8k16.row.col.f32.f16.f16.f32 "
        "{%0,%1,%2,%3}, {%4,%5,%6,%7}, {%8,%9}, {%0,%1,%2,%3};"
        : "+f"(c[0]), "+f"(c[1]), "+f"(c[2]), "+f"(c[3])
        : "r"(a0), "r"(a1), "r"(a2), "r"(a3), "r"(b0), "r"(b1));
}

// Exclusive-prefix cumprod of cos over one 8-wide head held by a lane quad.
// Thread (tig = lane&3) holds cols 2*tig, 2*tig+1 of its row.
static __device__ __forceinline__ float2 head_scan(float v0, float v1, int tig) {
    const float c0 = __cosf(v0);
    const float c1 = __cosf(v1);
    const float p = c0 * c1;
    const float pm1 = __shfl_up_sync(0xffffffffu, p, 1, 4);
    const float pm2 = __shfl_up_sync(0xffffffffu, p, 2, 4);
    const float pm3 = __shfl_up_sync(0xffffffffu, p, 3, 4);
    float ex = 1.0f;
    if (tig >= 1) ex *= pm1;
    if (tig >= 2) ex *= pm2;
    if (tig >= 3) ex *= pm3;
    float2 r;
    r.x = ex * c0;      // cumprod through col 2*tig
    r.y = ex * p;       // cumprod through col 2*tig+1
    return r;
}

// ---------------------------------------------------------------------------
// fp32 -> fp16 (rne): DST 0 = x, 1 = Wq, 2 = Wo
// ---------------------------------------------------------------------------
template <int DST>
__global__ void cvt_half(const float* __restrict__ src) {
    __half* __restrict__ dst = (DST == 0) ? g_xh : (DST == 1) ? g_wq : g_wo;
    const size_t i = ((size_t)blockIdx.x * blockDim.x + threadIdx.x) * 8;
    const float4 v0 = *(const float4*)(src + i);
    const float4 v1 = *(const float4*)(src + i + 4);
    const __half2 h0 = __floats2half2_rn(v0.x, v0.y);
    const __half2 h1 = __floats2half2_rn(v0.z, v0.w);
    const __half2 h2 = __floats2half2_rn(v1.x, v1.y);
    const __half2 h3 = __floats2half2_rn(v1.z, v1.w);
    uint4 o;
    o.x = *(const uint32_t*)&h0;
    o.y = *(const uint32_t*)&h1;
    o.z = *(const uint32_t*)&h2;
    o.w = *(const uint32_t*)&h3;
    *(uint4*)(dst + i) = o;
}

// ---------------------------------------------------------------------------
// D[m_base.., n_base..] = A . W^T over K=512.  4 warps, warp tile 64x64.
// MEASURE: epilogue = cos+cumprod8 along n -> g_meash.  else -> Outp (fp32).
// ---------------------------------------------------------------------------
template <bool MEASURE>
__global__ void __launch_bounds__(NTHREADS, 2) qgemm(float* __restrict__ Outp) {
    extern __shared__ __half smh[];
    const uint32_t sb = smem_u32(smh);
    const int tid = threadIdx.x;
    const int wid = tid >> 5;
    const int lane = tid & 31;
    const int g = lane >> 2;       // group id (row / n within fragment)
    const int tig = lane & 3;      // k-pair selector

    // N-tiles vary fastest (blockIdx.x) so wave-adjacent CTAs share A rows in L2
    const int n_base = blockIdx.x * BN;
    const int m_base = blockIdx.y * BM;

    const __half* __restrict__ A = MEASURE ? g_xh : g_meash;
    const __half* __restrict__ W = MEASURE ? g_wq : g_wo;

    // ---- async stage loader: A 128x64h + B 128x64h, 16B granules ----
    // per tile: 128 rows x 8 granules (8 halves each) = 1024 granules
    auto load_stage = [&](int s, int kb) {
        const uint32_t sa = sb + (uint32_t)(s * STAGE_H) * 2u;
        const uint32_t sw = sa + (uint32_t)TILE_H * 2u;
#pragma unroll
        for (int i = 0; i < 8; i++) {
            const int p = tid + i * NTHREADS;
            const int row = p >> 3;
            const int c = p & 7;
            cp_async16(sa + (uint32_t)(row * AH + c * 8) * 2u,
                       A + (size_t)(m_base + row) * KTOT + kb + c * 8);
        }
#pragma unroll
        for (int i = 0; i < 8; i++) {
            const int p = tid + i * NTHREADS;
            const int row = p >> 3;
            const int c = p & 7;
            cp_async16(sw + (uint32_t)(row * AH + c * 8) * 2u,
                       W + (size_t)(n_base + row) * KTOT + kb + c * 8);
        }
        cp_commit();
    };

    load_stage(0, 0);
    load_stage(1, BK);

    const int warp_m = wid & 1;    // 2 x 64 rows
    const int warp_n = wid >> 1;   // 2 x 64 cols

    float acc[4][8][4];
#pragma unroll
    for (int mt = 0; mt < 4; mt++)
#pragma unroll
        for (int nt = 0; nt < 8; nt++)
#pragma unroll
            for (int i = 0; i < 4; i++) acc[mt][nt][i] = 0.0f;

#pragma unroll 1
    for (int kc = 0; kc < NCHUNK; kc++) {
        if (kc == NCHUNK - 1) cp_wait0(); else cp_wait1();
        __syncthreads();

        // Prefetch next stage before compute (stage was consumed last iter;
        // the sync above ordered its readers).
        const int nk = kc + 2;
        if (nk < NCHUNK) load_stage(nk % NSTAGE, nk * BK);

        const uint32_t* smA =
            (const uint32_t*)(smh + (kc % NSTAGE) * STAGE_H);
        const uint32_t* smB = smA + TILE_H / 2;

#pragma unroll
        for (int ks = 0; ks < 4; ks++) {       // four k16 steps per chunk
            const int kk = ks * 8;             // half2 offset of this k16 block
            // A fragments: identity slot mapping.
            // a0=(row r,   k 2tig,2tig+1)  a1=(r+8, same)
            // a2=(row r,   k 8+2tig..)     a3=(r+8, same)
            uint32_t af[4][4];
#pragma unroll
            for (int mt = 0; mt < 4; mt++) {
                const int r = warp_m * 64 + mt * 16 + g;
                af[mt][0] = smA[r * AH2 + kk + tig];
                af[mt][1] = smA[(r + 8) * AH2 + kk + tig];
                af[mt][2] = smA[r * AH2 + kk + tig + 4];
                af[mt][3] = smA[(r + 8) * AH2 + kk + tig + 4];
            }
            uint32_t bf[8][2];
#pragma unroll
            for (int nt = 0; nt < 8; nt++) {
                const int n = warp_n * 64 + nt * 8 + g;
                bf[nt][0] = smB[n * AH2 + kk + tig];        // k 2tig,2tig+1
                bf[nt][1] = smB[n * AH2 + kk + tig + 4];    // k 8+2tig..
            }
#pragma unroll
            for (int mt = 0; mt < 4; mt++)
#pragma unroll
                for (int nt = 0; nt < 8; nt++)
                    mma_f16(acc[mt][nt], af[mt][0], af[mt][1], af[mt][2],
                            af[mt][3], bf[nt][0], bf[nt][1]);
        }
    }

    // ---- epilogue: c0=(g,2tig) c1=(g,2tig+1) c2=(g+8,2tig) c3=(g+8,2tig+1)
#pragma unroll
    for (int mt = 0; mt < 4; mt++) {
#pragma unroll
        for (int nt = 0; nt < 8; nt++) {
            const int r0 = m_base + warp_m * 64 + mt * 16 + g;
            const int n0 = n_base + warp_n * 64 + nt * 8 + 2 * tig;
            const float* c = acc[mt][nt];
            if (MEASURE) {
                // each m16n8 tile spans exactly one 8-wide head
                const float2 lo = head_scan(c[0], c[1], tig);   // row r0
                const float2 hi = head_scan(c[2], c[3], tig);   // row r0+8
                const __half2 hlo = __floats2half2_rn(lo.x, lo.y);
                const __half2 hhi = __floats2half2_rn(hi.x, hi.y);
                *(__half2*)(g_meash + (size_t)r0 * KTOT + n0) = hlo;
                *(__half2*)(g_meash + (size_t)(r0 + 8) * KTOT + n0) = hhi;
            } else {
                *(float2*)(Outp + (size_t)r0 * KTOT + n0) =
                    make_float2(c[0], c[1]);
                *(float2*)(Outp + (size_t)(r0 + 8) * KTOT + n0) =
                    make_float2(c[2], c[3]);
            }
        }
    }
}

// ---------------------------------------------------------------------------
// Inputs (metadata order): x, Wq, Wk, Wv, Wo.  Wk/Wv are dead compute.
// ---------------------------------------------------------------------------
extern "C" void kernel_launch(void* const* d_in, const int* in_sizes, int n_in,
                              void* d_out, int out_size) {
    const float* x = (const float*)d_in[0];
    const float* Wq = (const float*)d_in[1];
    const float* Wo = (const float*)d_in[4];

    static bool attr_set = false;
    if (!attr_set) {
        cudaFuncSetAttribute(qgemm<true>,
                             cudaFuncAttributeMaxDynamicSharedMemorySize,
                             SMEM_BYTES);
        cudaFuncSetAttribute(qgemm<false>,
                             cudaFuncAttributeMaxDynamicSharedMemorySize,
                             SMEM_BYTES);
        attr_set = true;
    }

    const size_t XN = (size_t)MTOT * KTOT;   // 16777216
    const size_t WN = (size_t)KTOT * KTOT;   // 262144
    cvt_half<0><<<(unsigned)(XN / (256 * 8)), 256>>>(x);
    cvt_half<1><<<(unsigned)(WN / (256 * 8)), 256>>>(Wq);
    cvt_half<2><<<(unsigned)(WN / (256 * 8)), 256>>>(Wo);

    dim3 grid(KTOT / BN, MTOT / BM);  // (4, 256): n fastest for L2 reuse of A
    qgemm<true><<<grid, NTHREADS, SMEM_BYTES>>>(nullptr);
    qgemm<false><<<grid, NTHREADS, SMEM_BYTES>>>((float*)d_out);
}

// round 15
// speedup vs baseline: 1.7941x; 1.0270x over previous
#include <cuda_runtime.h>
#include <cuda_fp16.h>
#include <cstdint>

// ============================================================================
// R15 = R14 (passing, 153.6us) with ONE change: fragment loads via
// ldmatrix.m8n8.x4 (4 LDSM per operand per k16 step) instead of 16 scalar
// LDS — identical fragment contents, identical MMA order => bit-identical.
//   pre:  x, Wq, Wo -> half (rne)
//   K1: meas = cumprod8(cos(x_h @ Wq_h^T)) -> g_meash (half)
//   K2: out  = meas_h @ Wo_h^T             -> d_out (fp32)
// k/v are dead compute in the reference; skipped.
// ============================================================================

#define BM 128
#define BN 128
#define BK 64                        // halves of K per chunk (4 k16 steps)
#define KTOT 512
#define MTOT 32768
#define NCHUNK (KTOT / BK)           // 8
#define NTHREADS 128

#define AH 72                        // halves per smem row (64 + 8 pad) = 144B
#define AH2 (AH / 2)                 // half2 words per row = 36
#define TILE_H (BM * AH)             // 9216 halves per tile
#define STAGE_H (2 * TILE_H)         // A + B
#define NSTAGE 3
#define SMEM_BYTES (NSTAGE * STAGE_H * 2)   // 110592 B

// Device scratch (static arrays; no runtime allocation)
__device__ __half g_xh[(size_t)MTOT * KTOT];     // 32 MB
__device__ __half g_meash[(size_t)MTOT * KTOT];  // 32 MB
__device__ __half g_wq[KTOT * KTOT];             // 512 KB
__device__ __half g_wo[KTOT * KTOT];             // 512 KB

// ---------------------------------------------------------------------------
static __device__ __forceinline__ uint32_t smem_u32(const void* p) {
    uint32_t a;
    asm("{ .reg .u64 t; cvta.to.shared.u64 t, %1; cvt.u32.u64 %0, t; }"
        : "=r"(a) : "l"(p));
    return a;
}

static __device__ __forceinline__ void cp_async16(uint32_t dst, const void* src) {
    asm volatile("cp.async.cg.shared.global [%0], [%1], 16;"
                 :: "r"(dst), "l"(src) : "memory");
}
static __device__ __forceinline__ void cp_commit() {
    asm volatile("cp.async.commit_group;" ::: "memory");
}
static __device__ __forceinline__ void cp_wait1() {
    asm volatile("cp.async.wait_group 1;" ::: "memory");
}
static __device__ __forceinline__ void cp_wait0() {
    asm volatile("cp.async.wait_group 0;" ::: "memory");
}

static __device__ __forceinline__ void ldsm_x4(
    uint32_t addr, uint32_t& r0, uint32_t& r1, uint32_t& r2, uint32_t& r3) {
    asm volatile("ldmatrix.sync.aligned.m8n8.x4.shared.b16 {%0,%1,%2,%3}, [%4];"
                 : "=r"(r0), "=r"(r1), "=r"(r2), "=r"(r3) : "r"(addr));
}

// m16n8k16 fp16 inputs, fp32 accumulate
static __device__ __forceinline__ void mma_f16(
    float* c, uint32_t a0, uint32_t a1, uint32_t a2, uint32_t a3,
    uint32_t b0, uint32_t b1) {
    asm volatile(
        "mma.sync.aligned.m16n8k16.row.col.f32.f16.f16.f32 "
        "{%0,%1,%2,%3}, {%4,%5,%6,%7}, {%8,%9}, {%0,%1,%2,%3};"
        : "+f"(c[0]), "+f"(c[1]), "+f"(c[2]), "+f"(c[3])
        : "r"(a0), "r"(a1), "r"(a2), "r"(a3), "r"(b0), "r"(b1));
}

// Exclusive-prefix cumprod of cos over one 8-wide head held by a lane quad.
// Thread (tig = lane&3) holds cols 2*tig, 2*tig+1 of its row.
static __device__ __forceinline__ float2 head_scan(float v0, float v1, int tig) {
    const float c0 = __cosf(v0);
    const float c1 = __cosf(v1);
    const float p = c0 * c1;
    const float pm1 = __shfl_up_sync(0xffffffffu, p, 1, 4);
    const float pm2 = __shfl_up_sync(0xffffffffu, p, 2, 4);
    const float pm3 = __shfl_up_sync(0xffffffffu, p, 3, 4);
    float ex = 1.0f;
    if (tig >= 1) ex *= pm1;
    if (tig >= 2) ex *= pm2;
    if (tig >= 3) ex *= pm3;
    float2 r;
    r.x = ex * c0;      // cumprod through col 2*tig
    r.y = ex * p;       // cumprod through col 2*tig+1
    return r;
}

// ---------------------------------------------------------------------------
// fp32 -> fp16 (rne): DST 0 = x, 1 = Wq, 2 = Wo
// ---------------------------------------------------------------------------
template <int DST>
__global__ void cvt_half(const float* __restrict__ src) {
    __half* __restrict__ dst = (DST == 0) ? g_xh : (DST == 1) ? g_wq : g_wo;
    const size_t i = ((size_t)blockIdx.x * blockDim.x + threadIdx.x) * 8;
    const float4 v0 = *(const float4*)(src + i);
    const float4 v1 = *(const float4*)(src + i + 4);
    const __half2 h0 = __floats2half2_rn(v0.x, v0.y);
    const __half2 h1 = __floats2half2_rn(v0.z, v0.w);
    const __half2 h2 = __floats2half2_rn(v1.x, v1.y);
    const __half2 h3 = __floats2half2_rn(v1.z, v1.w);
    uint4 o;
    o.x = *(const uint32_t*)&h0;
    o.y = *(const uint32_t*)&h1;
    o.z = *(const uint32_t*)&h2;
    o.w = *(const uint32_t*)&h3;
    *(uint4*)(dst + i) = o;
}

// ---------------------------------------------------------------------------
// D[m_base.., n_base..] = A . W^T over K=512.  4 warps, warp tile 64x64.
// MEASURE: epilogue = cos+cumprod8 along n -> g_meash.  else -> Outp (fp32).
// ---------------------------------------------------------------------------
template <bool MEASURE>
__global__ void __launch_bounds__(NTHREADS, 2) qgemm(float* __restrict__ Outp) {
    extern __shared__ __half smh[];
    const uint32_t sb = smem_u32(smh);
    const int tid = threadIdx.x;
    const int wid = tid >> 5;
    const int lane = tid & 31;
    const int g = lane >> 2;       // group id (row / n within fragment)
    const int tig = lane & 3;      // k-pair selector
    const int lrow = lane & 7;     // ldmatrix: row within 8x8 matrix
    const int lm = lane >> 3;      // ldmatrix: matrix id 0..3

    // N-tiles vary fastest (blockIdx.x) so wave-adjacent CTAs share A rows in L2
    const int n_base = blockIdx.x * BN;
    const int m_base = blockIdx.y * BM;

    const __half* __restrict__ A = MEASURE ? g_xh : g_meash;
    const __half* __restrict__ W = MEASURE ? g_wq : g_wo;

    // ---- async stage loader: A 128x64h + B 128x64h, 16B granules ----
    auto load_stage = [&](int s, int kb) {
        const uint32_t sa = sb + (uint32_t)(s * STAGE_H) * 2u;
        const uint32_t sw = sa + (uint32_t)TILE_H * 2u;
#pragma unroll
        for (int i = 0; i < 8; i++) {
            const int p = tid + i * NTHREADS;
            const int row = p >> 3;
            const int c = p & 7;
            cp_async16(sa + (uint32_t)(row * AH + c * 8) * 2u,
                       A + (size_t)(m_base + row) * KTOT + kb + c * 8);
        }
#pragma unroll
        for (int i = 0; i < 8; i++) {
            const int p = tid + i * NTHREADS;
            const int row = p >> 3;
            const int c = p & 7;
            cp_async16(sw + (uint32_t)(row * AH + c * 8) * 2u,
                       W + (size_t)(n_base + row) * KTOT + kb + c * 8);
        }
        cp_commit();
    };

    load_stage(0, 0);
    load_stage(1, BK);

    const int warp_m = wid & 1;    // 2 x 64 rows
    const int warp_n = wid >> 1;   // 2 x 64 cols

    // ldmatrix per-lane offsets (halves), matching the identity fragment map:
    // A mats 0..3 = (r,k0),(r+8,k0),(r,k8),(r+8,k8)
    const int aoff = ((lm & 1) * 8 + lrow) * AH + (lm >> 1) * 8;
    // B mats 0..3 = (n0-7,k0),(n0-7,k8),(n8-15,k0),(n8-15,k8)
    const int boff = ((lm >> 1) * 8 + lrow) * AH + (lm & 1) * 8;

    float acc[4][8][4];
#pragma unroll
    for (int mt = 0; mt < 4; mt++)
#pragma unroll
        for (int nt = 0; nt < 8; nt++)
#pragma unroll
            for (int i = 0; i < 4; i++) acc[mt][nt][i] = 0.0f;

#pragma unroll 1
    for (int kc = 0; kc < NCHUNK; kc++) {
        if (kc == NCHUNK - 1) cp_wait0(); else cp_wait1();
        __syncthreads();

        // Prefetch next stage before compute (stage was consumed last iter;
        // the sync above ordered its readers).
        const int nk = kc + 2;
        if (nk < NCHUNK) load_stage(nk % NSTAGE, nk * BK);

        const uint32_t baseA = sb + (uint32_t)((kc % NSTAGE) * STAGE_H) * 2u;
        const uint32_t baseB = baseA + (uint32_t)TILE_H * 2u;

#pragma unroll
        for (int ks = 0; ks < 4; ks++) {       // four k16 steps per chunk
            const int kh = ks * 16;            // half offset of this k16 block
            uint32_t af[4][4];
#pragma unroll
            for (int mt = 0; mt < 4; mt++)
                ldsm_x4(baseA +
                            (uint32_t)((warp_m * 64 + mt * 16) * AH + kh + aoff) * 2u,
                        af[mt][0], af[mt][1], af[mt][2], af[mt][3]);
            uint32_t bf[8][2];
#pragma unroll
            for (int p = 0; p < 4; p++)
                ldsm_x4(baseB +
                            (uint32_t)((warp_n * 64 + p * 16) * AH + kh + boff) * 2u,
                        bf[2 * p][0], bf[2 * p][1], bf[2 * p + 1][0],
                        bf[2 * p + 1][1]);
#pragma unroll
            for (int mt = 0; mt < 4; mt++)
#pragma unroll
                for (int nt = 0; nt < 8; nt++)
                    mma_f16(acc[mt][nt], af[mt][0], af[mt][1], af[mt][2],
                            af[mt][3], bf[nt][0], bf[nt][1]);
        }
    }

    // ---- epilogue: c0=(g,2tig) c1=(g,2tig+1) c2=(g+8,2tig) c3=(g+8,2tig+1)
#pragma unroll
    for (int mt = 0; mt < 4; mt++) {
#pragma unroll
        for (int nt = 0; nt < 8; nt++) {
            const int r0 = m_base + warp_m * 64 + mt * 16 + g;
            const int n0 = n_base + warp_n * 64 + nt * 8 + 2 * tig;
            const float* c = acc[mt][nt];
            if (MEASURE) {
                // each m16n8 tile spans exactly one 8-wide head
                const float2 lo = head_scan(c[0], c[1], tig);   // row r0
                const float2 hi = head_scan(c[2], c[3], tig);   // row r0+8
                const __half2 hlo = __floats2half2_rn(lo.x, lo.y);
                const __half2 hhi = __floats2half2_rn(hi.x, hi.y);
                *(__half2*)(g_meash + (size_t)r0 * KTOT + n0) = hlo;
                *(__half2*)(g_meash + (size_t)(r0 + 8) * KTOT + n0) = hhi;
            } else {
                *(float2*)(Outp + (size_t)r0 * KTOT + n0) =
                    make_float2(c[0], c[1]);
                *(float2*)(Outp + (size_t)(r0 + 8) * KTOT + n0) =
                    make_float2(c[2], c[3]);
            }
        }
    }
}

// ---------------------------------------------------------------------------
// Inputs (metadata order): x, Wq, Wk, Wv, Wo.  Wk/Wv are dead compute.
// ---------------------------------------------------------------------------
extern "C" void kernel_launch(void* const* d_in, const int* in_sizes, int n_in,
                              void* d_out, int out_size) {
    const float* x = (const float*)d_in[0];
    const float* Wq = (const float*)d_in[1];
    const float* Wo = (const float*)d_in[4];

    static bool attr_set = false;
    if (!attr_set) {
        cudaFuncSetAttribute(qgemm<true>,
                             cudaFuncAttributeMaxDynamicSharedMemorySize,
                             SMEM_BYTES);
        cudaFuncSetAttribute(qgemm<false>,
                             cudaFuncAttributeMaxDynamicSharedMemorySize,
                             SMEM_BYTES);
        attr_set = true;
    }

    const size_t XN = (size_t)MTOT * KTOT;   // 16777216
    const size_t WN = (size_t)KTOT * KTOT;   // 262144
    cvt_half<0><<<(unsigned)(XN / (256 * 8)), 256>>>(x);
    cvt_half<1><<<(unsigned)(WN / (256 * 8)), 256>>>(Wq);
    cvt_half<2><<<(unsigned)(WN / (256 * 8)), 256>>>(Wo);

    dim3 grid(KTOT / BN, MTOT / BM);  // (4, 256): n fastest for L2 reuse of A
    qgemm<true><<<grid, NTHREADS, SMEM_BYTES>>>(nullptr);
    qgemm<false><<<grid, NTHREADS, SMEM_BYTES>>>((float*)d_out);
}